// round 5
// baseline (speedup 1.0000x reference)
#include <cuda_runtime.h>
#include <cuda_bf16.h>
#include <cstdint>

#define NN 6400
#define CC 64
#define CP 128          // augmented K: [hi | lo] bf16
#define HH 80
#define SSTR 72
#define ASPLIT 5        // column splits in pass A
#define ATILES 10       // 128-col tiles per split (50/5)

// augmented bf16 operand matrix P = [bf16(x) | bf16(x - bf16(x))]
__device__ __nv_bfloat16 g_P[(size_t)NN * CP];
// per-(split,row) online-softmax partials (m, s)
__device__ float2 g_MS[ASPLIT][NN];
__device__ float g_M[NN];
__device__ float g_Z[NN];

// ---------------------------------------------------------------------------
__device__ __forceinline__ void mma16816(float* c, const uint32_t* a,
                                         const uint32_t* b) {
    asm volatile(
        "mma.sync.aligned.m16n8k16.row.col.f32.bf16.bf16.f32 "
        "{%0,%1,%2,%3}, {%4,%5,%6,%7}, {%8,%9}, {%0,%1,%2,%3};"
        : "+f"(c[0]), "+f"(c[1]), "+f"(c[2]), "+f"(c[3])
        : "r"(a[0]), "r"(a[1]), "r"(a[2]), "r"(a[3]),
          "r"(b[0]), "r"(b[1]));
}

// stage one 64-k chunk of 128 rows from g_P into padded smem
__device__ __forceinline__ void stage_tile(__nv_bfloat16* s, int row0,
                                           int kc, int ldrow, int ldhalf) {
    const uint4* src = reinterpret_cast<const uint4*>(
        g_P + (size_t)(row0 + ldrow) * CP + kc * 64 + ldhalf);
    uint4* dst = reinterpret_cast<uint4*>(&s[ldrow * SSTR + ldhalf]);
    dst[0] = src[0]; dst[1] = src[1]; dst[2] = src[2]; dst[3] = src[3];
}

// ---------------------------------------------------------------------------
// kprep: build P. One thread = 8 consecutive floats of one row.
// ---------------------------------------------------------------------------
__global__ __launch_bounds__(256) void kprep(const float* __restrict__ X) {
    int t = blockIdx.x * 256 + threadIdx.x;
    int row = t >> 3;
    int seg = (t & 7) * 8;
    const float* src = X + (size_t)row * CC + seg;
    __nv_bfloat16* hi = g_P + (size_t)row * CP + seg;
    __nv_bfloat16* lo = hi + CC;
    #pragma unroll
    for (int i = 0; i < 8; i++) {
        float x = src[i];
        __nv_bfloat16 h = __float2bfloat16_rn(x);
        float r = x - __bfloat162float(h);
        hi[i] = h;
        lo[i] = __float2bfloat16_rn(r);
    }
}

// ---------------------------------------------------------------------------
// kA: pass A — full GEMM over a 128-row band x 1280-col split with online
// per-row (max, sum-exp). No logit stores.
// ---------------------------------------------------------------------------
__global__ __launch_bounds__(256) void kA() {
    __shared__ __nv_bfloat16 sA[128 * SSTR];
    __shared__ __nv_bfloat16 sB[128 * SSTR];
    __shared__ float2 sMS[2][128];

    const int tid  = threadIdx.x;
    const int lane = tid & 31;
    const int wid  = tid >> 5;
    const int warpM = wid & 3;
    const int warpN = wid >> 2;
    const int g  = lane >> 2;
    const int tg = lane & 3;
    const int r0 = blockIdx.y * 128;
    const int cbase = blockIdx.x * (128 * ATILES);
    const int ldrow = tid >> 1;
    const int ldhalf = (tid & 1) * 32;

    float m_run[4] = {-3.0e38f, -3.0e38f, -3.0e38f, -3.0e38f};
    float s_run[4] = {0.0f, 0.0f, 0.0f, 0.0f};

    for (int ct = 0; ct < ATILES; ct++) {
        const int c0 = cbase + ct * 128;
        float acc[2][8][4];
        #pragma unroll
        for (int mt = 0; mt < 2; mt++)
            #pragma unroll
            for (int nt = 0; nt < 8; nt++)
                #pragma unroll
                for (int i = 0; i < 4; i++)
                    acc[mt][nt][i] = 0.0f;

        #pragma unroll
        for (int kc = 0; kc < 2; kc++) {
            __syncthreads();
            stage_tile(sA, r0, kc, ldrow, ldhalf);
            stage_tile(sB, c0, kc, ldrow, ldhalf);
            __syncthreads();

            #pragma unroll
            for (int t = 0; t < 4; t++) {
                const int kb = t * 16;
                uint32_t afr[2][4];
                #pragma unroll
                for (int mt = 0; mt < 2; mt++) {
                    int r = warpM * 32 + mt * 16 + g;
                    afr[mt][0] = *reinterpret_cast<const uint32_t*>(&sA[r * SSTR + kb + tg * 2]);
                    afr[mt][1] = *reinterpret_cast<const uint32_t*>(&sA[(r + 8) * SSTR + kb + tg * 2]);
                    afr[mt][2] = *reinterpret_cast<const uint32_t*>(&sA[r * SSTR + kb + 8 + tg * 2]);
                    afr[mt][3] = *reinterpret_cast<const uint32_t*>(&sA[(r + 8) * SSTR + kb + 8 + tg * 2]);
                }
                uint32_t bfr[8][2];
                #pragma unroll
                for (int nt = 0; nt < 8; nt++) {
                    int n = warpN * 64 + nt * 8 + g;
                    bfr[nt][0] = *reinterpret_cast<const uint32_t*>(&sB[n * SSTR + kb + tg * 2]);
                    bfr[nt][1] = *reinterpret_cast<const uint32_t*>(&sB[n * SSTR + kb + 8 + tg * 2]);
                }
                #pragma unroll
                for (int mt = 0; mt < 2; mt++)
                    #pragma unroll
                    for (int nt = 0; nt < 8; nt++)
                        mma16816(acc[mt][nt], afr[mt], bfr[nt]);
            }
        }

        // online (m, s) update — slot s: mt = s>>1, half = s&1
        #pragma unroll
        for (int s = 0; s < 4; s++) {
            const int mt = s >> 1, h2 = (s & 1) * 2;
            float vmax = -3.0e38f;
            #pragma unroll
            for (int nt = 0; nt < 8; nt++)
                vmax = fmaxf(vmax, fmaxf(acc[mt][nt][h2], acc[mt][nt][h2 + 1]));
            float mnew = fmaxf(m_run[s], vmax);
            float ssum = 0.0f;
            #pragma unroll
            for (int nt = 0; nt < 8; nt++)
                ssum += __expf(acc[mt][nt][h2] - mnew) +
                        __expf(acc[mt][nt][h2 + 1] - mnew);
            s_run[s] = s_run[s] * __expf(m_run[s] - mnew) + ssum;
            m_run[s] = mnew;
        }
    }

    // reduce across the 4 lanes of each quad (same g -> same rows)
    #pragma unroll
    for (int off = 1; off <= 2; off <<= 1) {
        #pragma unroll
        for (int s = 0; s < 4; s++) {
            float om = __shfl_xor_sync(0xFFFFFFFFu, m_run[s], off);
            float os = __shfl_xor_sync(0xFFFFFFFFu, s_run[s], off);
            float M = fmaxf(m_run[s], om);
            s_run[s] = s_run[s] * __expf(m_run[s] - M) + os * __expf(om - M);
            m_run[s] = M;
        }
    }
    if (tg == 0) {
        #pragma unroll
        for (int s = 0; s < 4; s++) {
            int rl = warpM * 32 + (s >> 1) * 16 + (s & 1) * 8 + g;
            sMS[warpN][rl] = make_float2(m_run[s], s_run[s]);
        }
    }
    __syncthreads();
    if (tid < 128) {
        float2 a = sMS[0][tid], b = sMS[1][tid];
        float M = fmaxf(a.x, b.x);
        float S = a.y * __expf(a.x - M) + b.y * __expf(b.x - M);
        g_MS[blockIdx.x][r0 + tid] = make_float2(M, S);
    }
}

// ---------------------------------------------------------------------------
// kms: merge the ASPLIT partials -> g_M (row max), g_Z (row sum of exp)
// ---------------------------------------------------------------------------
__global__ __launch_bounds__(256) void kms() {
    int r = blockIdx.x * 256 + threadIdx.x;   // 25 blocks
    float M = -3.0e38f, S = 0.0f;
    #pragma unroll
    for (int i = 0; i < ASPLIT; i++) {
        float2 p = g_MS[i][r];
        float Mn = fmaxf(M, p.x);
        S = S * __expf(M - Mn) + p.y * __expf(p.x - Mn);
        M = Mn;
    }
    g_M[r] = M;
    g_Z[r] = S;
}

// ---------------------------------------------------------------------------
// kB: pass B — GEMM again, fused softmax finalize + threshold, direct store.
// ---------------------------------------------------------------------------
__global__ __launch_bounds__(256, 2) void kB(float* __restrict__ As) {
    __shared__ __nv_bfloat16 sA[128 * SSTR];
    __shared__ __nv_bfloat16 sB[128 * SSTR];

    const int tid  = threadIdx.x;
    const int lane = tid & 31;
    const int wid  = tid >> 5;
    const int warpM = wid & 3;
    const int warpN = wid >> 2;
    const int g  = lane >> 2;
    const int tg = lane & 3;
    const int r0 = blockIdx.y * 128;
    const int c0 = blockIdx.x * 128;
    const int ldrow = tid >> 1;
    const int ldhalf = (tid & 1) * 32;

    // per-slot softmax params
    float pm[4], piz[4], pth[4];
    #pragma unroll
    for (int s = 0; s < 4; s++) {
        int row = r0 + warpM * 32 + (s >> 1) * 16 + (s & 1) * 8 + g;
        float Z = g_Z[row];
        pm[s]  = g_M[row];
        piz[s] = 1.0f / Z;
        pth[s] = Z * (1.0f / (float)NN);
    }

    float acc[2][8][4];
    #pragma unroll
    for (int mt = 0; mt < 2; mt++)
        #pragma unroll
        for (int nt = 0; nt < 8; nt++)
            #pragma unroll
            for (int i = 0; i < 4; i++)
                acc[mt][nt][i] = 0.0f;

    #pragma unroll
    for (int kc = 0; kc < 2; kc++) {
        if (kc) __syncthreads();
        stage_tile(sA, r0, kc, ldrow, ldhalf);
        stage_tile(sB, c0, kc, ldrow, ldhalf);
        __syncthreads();

        #pragma unroll
        for (int t = 0; t < 4; t++) {
            const int kb = t * 16;
            uint32_t afr[2][4];
            #pragma unroll
            for (int mt = 0; mt < 2; mt++) {
                int r = warpM * 32 + mt * 16 + g;
                afr[mt][0] = *reinterpret_cast<const uint32_t*>(&sA[r * SSTR + kb + tg * 2]);
                afr[mt][1] = *reinterpret_cast<const uint32_t*>(&sA[(r + 8) * SSTR + kb + tg * 2]);
                afr[mt][2] = *reinterpret_cast<const uint32_t*>(&sA[r * SSTR + kb + 8 + tg * 2]);
                afr[mt][3] = *reinterpret_cast<const uint32_t*>(&sA[(r + 8) * SSTR + kb + 8 + tg * 2]);
            }
            uint32_t bfr[8][2];
            #pragma unroll
            for (int nt = 0; nt < 8; nt++) {
                int n = warpN * 64 + nt * 8 + g;
                bfr[nt][0] = *reinterpret_cast<const uint32_t*>(&sB[n * SSTR + kb + tg * 2]);
                bfr[nt][1] = *reinterpret_cast<const uint32_t*>(&sB[n * SSTR + kb + 8 + tg * 2]);
            }
            #pragma unroll
            for (int mt = 0; mt < 2; mt++)
                #pragma unroll
                for (int nt = 0; nt < 8; nt++)
                    mma16816(acc[mt][nt], afr[mt], bfr[nt]);
        }
    }

    // fused softmax epilogue
    #pragma unroll
    for (int mt = 0; mt < 2; mt++) {
        const int s0 = mt * 2, s1 = mt * 2 + 1;
        #pragma unroll
        for (int nt = 0; nt < 8; nt++) {
            int row = r0 + warpM * 32 + mt * 16 + g;
            int col = c0 + warpN * 64 + nt * 8 + tg * 2;
            float e0 = __expf(acc[mt][nt][0] - pm[s0]);
            float e1 = __expf(acc[mt][nt][1] - pm[s0]);
            float e2 = __expf(acc[mt][nt][2] - pm[s1]);
            float e3 = __expf(acc[mt][nt][3] - pm[s1]);
            float2 v0, v1;
            v0.x = (e0 < pth[s0]) ? 0.0f : e0 * piz[s0];
            v0.y = (e1 < pth[s0]) ? 0.0f : e1 * piz[s0];
            v1.x = (e2 < pth[s1]) ? 0.0f : e2 * piz[s1];
            v1.y = (e3 < pth[s1]) ? 0.0f : e3 * piz[s1];
            *reinterpret_cast<float2*>(&As[(size_t)row * NN + col]) = v0;
            *reinterpret_cast<float2*>(&As[(size_t)(row + 8) * NN + col]) = v1;
        }
    }
}

// ---------------------------------------------------------------------------
// k3: analytic Ad. Tables built per block, grid-stride amortized.
// ---------------------------------------------------------------------------
#define ADBLK 4000
#define ADIT 10

__global__ __launch_bounds__(256) void k3_ad(float* __restrict__ Ad) {
    __shared__ float sE[HH];
    __shared__ float sS1[HH];
    int tid = threadIdx.x;
    if (tid < HH) sE[tid] = __expf(-0.5f * (float)(tid * tid));
    __syncthreads();
    if (tid < HH) {
        float s = 0.0f;
        #pragma unroll 8
        for (int r = 0; r < HH; r++) {
            int d = tid - r; d = d < 0 ? -d : d;
            s += sE[d];
        }
        sS1[tid] = s;
    }
    __syncthreads();

    #pragma unroll
    for (int it = 0; it < ADIT; it++) {
        size_t q = (size_t)blockIdx.x * (256 * ADIT) + it * 256 + tid;
        size_t e = q * 4;
        int i  = (int)(e / NN);
        int j0 = (int)(e - (size_t)i * NN);
        int ri = i / HH,  ci = i - ri * HH;
        int rj = j0 / HH, cj = j0 - rj * HH;

        int dr = ri - rj; dr = dr < 0 ? -dr : dr;
        float inv  = 1.0f / (sS1[ri] * sS1[ci] - 1.0f);
        float base = sE[dr] * inv;

        int d0 = ci - cj;       d0 = d0 < 0 ? -d0 : d0;
        int d1 = ci - (cj + 1); d1 = d1 < 0 ? -d1 : d1;
        int d2 = ci - (cj + 2); d2 = d2 < 0 ? -d2 : d2;
        int d3 = ci - (cj + 3); d3 = d3 < 0 ? -d3 : d3;
        float4 o;
        o.x = base * sE[d0];
        o.y = base * sE[d1];
        o.z = base * sE[d2];
        o.w = base * sE[d3];
        if (i == j0    ) o.x = 0.0f;
        if (i == j0 + 1) o.y = 0.0f;
        if (i == j0 + 2) o.z = 0.0f;
        if (i == j0 + 3) o.w = 0.0f;
        reinterpret_cast<float4*>(Ad)[q] = o;
    }
}

// ---------------------------------------------------------------------------
extern "C" void kernel_launch(void* const* d_in, const int* in_sizes, int n_in,
                              void* d_out, int out_size) {
    const float* X = (const float*)d_in[0];
    float* Ad = (float*)d_out;                       // first N*N floats
    float* As = (float*)d_out + (size_t)NN * NN;     // second N*N floats

    kprep<<<200, 256>>>(X);
    kA<<<dim3(ASPLIT, NN / 128), 256>>>();           // 5 x 50 CTAs
    kms<<<NN / 256, 256>>>();
    k3_ad<<<ADBLK, 256>>>(Ad);
    kB<<<dim3(NN / 128, NN / 128), 256>>>(As);       // 50 x 50 CTAs
}